// round 7
// baseline (speedup 1.0000x reference)
#include <cuda_runtime.h>
#include <cuda_bf16.h>
#include <math_constants.h>

// Problem shape (fixed by the reference)
#define L_DIM 1024
#define B_DIM 64
#define H_DIM 1024

#define SPLITS 4                        // grid (4, 64) = 256 CTAs, occ 2
#define WARPS_PER_BLOCK 8
#define ROWS_PER_SPLIT (L_DIM / SPLITS) // 256
#define HV 8                            // float4 vectors per thread (H/128)

// Scratch: per-(b,split) context vector + (M, D). 1 MB total.
__device__ float g_ctx[B_DIM * SPLITS * H_DIM];
__device__ float g_m[B_DIM * SPLITS];
__device__ float g_d[B_DIM * SPLITS];
__device__ int   g_cnt[B_DIM];          // zero-initialized; reset by last CTA each run

// Non-CSE-able L1-cached reload (row is guaranteed L1-resident from first pass).
__device__ __forceinline__ float4 ldg_ca_f4(const float4* p) {
    float4 v;
    asm volatile("ld.global.ca.v4.f32 {%0,%1,%2,%3}, [%4];"
                 : "=f"(v.x), "=f"(v.y), "=f"(v.z), "=f"(v.w)
                 : "l"(p));
    return v;
}

// ---------------------------------------------------------------------------
// Fused kernel, software-pipelined rows:
//   iter n: dot(ev_n) -> prefetch ev_{n+1} -> shfl/softmax -> acc update via
//   L1 reload of row n. Next row's DRAM latency hides under row n's reduce.
// grid: (SPLITS, B) = 256 CTAs, block 256 (8 warps), occ 2 -> single wave.
// ---------------------------------------------------------------------------
__global__ __launch_bounds__(256, 2)
void attn_fused(const float* __restrict__ enc,   // [L, B, H]
                const float* __restrict__ dec,   // [1, B, H]
                float* __restrict__ out)         // [B, H]
{
    const int s    = blockIdx.x;
    const int b    = blockIdx.y;
    const int warp = threadIdx.x >> 5;
    const int lane = threadIdx.x & 31;

    __shared__ float s_acc[WARPS_PER_BLOCK][H_DIM];   // 32 KB
    __shared__ float s_m[WARPS_PER_BLOCK];
    __shared__ float s_d[WARPS_PER_BLOCK];
    __shared__ float s_scale[WARPS_PER_BLOCK];
    __shared__ int   s_is_last;

    // Decoder slice in registers: h = k*128 + lane*4
    const float4* dec4 = reinterpret_cast<const float4*>(dec + (size_t)b * H_DIM);
    float4 dv[HV];
#pragma unroll
    for (int k = 0; k < HV; k++) dv[k] = dec4[k * 32 + lane];

    float4 acc[HV];
#pragma unroll
    for (int k = 0; k < HV; k++) acc[k] = make_float4(0.f, 0.f, 0.f, 0.f);
    float m = -CUDART_INF_F;
    float d = 0.f;

    const int l0 = s * ROWS_PER_SPLIT + warp;
    const int l1 = (s + 1) * ROWS_PER_SPLIT;

    // Prologue: load first row (L1-caching loads).
    const float4* cur =
        reinterpret_cast<const float4*>(enc + ((size_t)l0 * B_DIM + b) * H_DIM);
    float4 ev[HV];
#pragma unroll
    for (int k = 0; k < HV; k++) ev[k] = cur[k * 32 + lane];

    for (int l = l0; l < l1; l += WARPS_PER_BLOCK) {
        // ---- dot(ev, dv): consumes ev ----
        float sc = 0.f;
#pragma unroll
        for (int k = 0; k < HV; k++) {
            sc = fmaf(ev[k].x, dv[k].x, sc);
            sc = fmaf(ev[k].y, dv[k].y, sc);
            sc = fmaf(ev[k].z, dv[k].z, sc);
            sc = fmaf(ev[k].w, dv[k].w, sc);
        }

        // ---- prefetch next row into ev (overwrites; clamped on last iter) ----
        const int ln = l + WARPS_PER_BLOCK;
        const float4* nxt = (ln < l1)
            ? reinterpret_cast<const float4*>(enc + ((size_t)ln * B_DIM + b) * H_DIM)
            : cur;
#pragma unroll
        for (int k = 0; k < HV; k++) ev[k] = nxt[k * 32 + lane];

        // ---- warp reduce + online softmax (branch-free, R3 form) ----
#pragma unroll
        for (int off = 16; off > 0; off >>= 1)
            sc += __shfl_xor_sync(0xffffffffu, sc, off);

        float nm    = fmaxf(m, sc);
        float alpha = __expf(m - nm);     // 0 on first iter (m = -inf)
        float w     = __expf(sc - nm);
        d = d * alpha + w;
        m = nm;

        // ---- accumulate row l via L1 reload (hits: row cached above) ----
#pragma unroll
        for (int k = 0; k < HV; k++) {
            float4 rv = ldg_ca_f4(&cur[k * 32 + lane]);
            acc[k].x = fmaf(w, rv.x, acc[k].x * alpha);
            acc[k].y = fmaf(w, rv.y, acc[k].y * alpha);
            acc[k].z = fmaf(w, rv.z, acc[k].z * alpha);
            acc[k].w = fmaf(w, rv.w, acc[k].w * alpha);
        }

        cur = nxt;
    }

    // ---- in-block flash combine of the 8 warp partials ----
#pragma unroll
    for (int k = 0; k < HV; k++)
        *reinterpret_cast<float4*>(&s_acc[warp][k * 128 + lane * 4]) = acc[k];
    if (lane == 0) { s_m[warp] = m; s_d[warp] = d; }
    __syncthreads();

    if (threadIdx.x == 0) {
        float M = -CUDART_INF_F;
#pragma unroll
        for (int w = 0; w < WARPS_PER_BLOCK; w++) M = fmaxf(M, s_m[w]);
        float D = 0.f;
#pragma unroll
        for (int w = 0; w < WARPS_PER_BLOCK; w++) {
            float sc = __expf(s_m[w] - M);
            s_scale[w] = sc;
            D += s_d[w] * sc;
        }
        const int pid = b * SPLITS + s;
        g_m[pid] = M;
        g_d[pid] = D;
    }
    __syncthreads();

    // Each thread reduces 4 h-positions across the 8 warp slots (float4).
    {
        const int h = threadIdx.x * 4;
        float4 sum = make_float4(0.f, 0.f, 0.f, 0.f);
#pragma unroll
        for (int w = 0; w < WARPS_PER_BLOCK; w++) {
            float sc = s_scale[w];
            float4 v = *reinterpret_cast<const float4*>(&s_acc[w][h]);
            sum.x = fmaf(sc, v.x, sum.x);
            sum.y = fmaf(sc, v.y, sum.y);
            sum.z = fmaf(sc, v.z, sum.z);
            sum.w = fmaf(sc, v.w, sum.w);
        }
        const int pid = b * SPLITS + s;
        *reinterpret_cast<float4*>(&g_ctx[(size_t)pid * H_DIM + h]) = sum;
    }

    // ---- last-CTA-per-b cross-split combine ----
    __threadfence();
    if (threadIdx.x == 0)
        s_is_last = (atomicAdd(&g_cnt[b], 1) == SPLITS - 1) ? 1 : 0;
    __syncthreads();
    if (!s_is_last) return;

    __threadfence();   // acquire: order reads of peers' partials after the atomic

    float M = -CUDART_INF_F;
#pragma unroll
    for (int p = 0; p < SPLITS; p++) M = fmaxf(M, g_m[b * SPLITS + p]);
    float D = 0.f;
    float scale[SPLITS];
#pragma unroll
    for (int p = 0; p < SPLITS; p++) {
        scale[p] = __expf(g_m[b * SPLITS + p] - M);
        D += g_d[b * SPLITS + p] * scale[p];
    }
    const float invD = 1.f / D;

    {
        const int h = threadIdx.x * 4;
        float4 sum = make_float4(0.f, 0.f, 0.f, 0.f);
#pragma unroll
        for (int p = 0; p < SPLITS; p++) {
            const float sc = scale[p] * invD;
            float4 v = *reinterpret_cast<const float4*>(
                &g_ctx[((size_t)(b * SPLITS + p)) * H_DIM + h]);
            sum.x = fmaf(sc, v.x, sum.x);
            sum.y = fmaf(sc, v.y, sum.y);
            sum.z = fmaf(sc, v.z, sum.z);
            sum.w = fmaf(sc, v.w, sum.w);
        }
        *reinterpret_cast<float4*>(&out[(size_t)b * H_DIM + h]) = sum;
    }

    if (threadIdx.x == 0) g_cnt[b] = 0;   // reset for next graph replay
}

// ---------------------------------------------------------------------------
extern "C" void kernel_launch(void* const* d_in, const int* in_sizes, int n_in,
                              void* d_out, int out_size)
{
    const float* enc = (const float*)d_in[0];   // [1024, 64, 1024]
    const float* dec = (const float*)d_in[1];   // [1, 64, 1024]
    float* out = (float*)d_out;                 // [64, 1024]

    dim3 grid(SPLITS, B_DIM);
    attn_fused<<<grid, 256>>>(enc, dec, out);
}

// round 9
// speedup vs baseline: 1.1429x; 1.1429x over previous
#include <cuda_runtime.h>
#include <cuda_bf16.h>
#include <math_constants.h>
#include <cstdint>

// Problem shape (fixed by the reference)
#define L_DIM 1024
#define B_DIM 64
#define H_DIM 1024

#define SPLITS 4                        // grid (4, 64) = 256 CTAs, occ 2
#define WARPS_PER_BLOCK 8
#define ROWS_PER_SPLIT (L_DIM / SPLITS) // 256
#define ROWS_PER_WARP (ROWS_PER_SPLIT / WARPS_PER_BLOCK)  // 32
#define HV 8                            // float4 vectors per thread (H/128)
#define STAGES 3                        // per-warp cp.async ring depth

#define RING_FLOATS (WARPS_PER_BLOCK * STAGES * H_DIM)   // 24576 floats = 96 KB

// Scratch: per-(b,split) context vector + (M, D). 1 MB total.
__device__ float g_ctx[B_DIM * SPLITS * H_DIM];
__device__ float g_m[B_DIM * SPLITS];
__device__ float g_d[B_DIM * SPLITS];
__device__ int   g_cnt[B_DIM];          // zero-initialized; reset by last CTA each run

#define CP_ASYNC16(dst_u32, src_ptr) \
    asm volatile("cp.async.cg.shared.global [%0], [%1], 16;" \
                 :: "r"(dst_u32), "l"(src_ptr) : "memory")
#define CP_COMMIT() asm volatile("cp.async.commit_group;" ::: "memory")
#define CP_WAIT(n)  asm volatile("cp.async.wait_group %0;" :: "n"(n) : "memory")

extern __shared__ float smem_dyn[];     // ring [8][3][1024]; reused as s_acc[8][1024]

// ---------------------------------------------------------------------------
// Fused kernel: cp.async 3-deep per-warp prefetch ring -> LDS -> branch-free
// online softmax + accumulation. grid (SPLITS, B) = 256 CTAs, block 256, occ 2.
// ---------------------------------------------------------------------------
__global__ __launch_bounds__(256, 2)
void attn_fused(const float* __restrict__ enc,   // [L, B, H]
                const float* __restrict__ dec,   // [1, B, H]
                float* __restrict__ out)         // [B, H]
{
    const int s    = blockIdx.x;
    const int b    = blockIdx.y;
    const int warp = threadIdx.x >> 5;
    const int lane = threadIdx.x & 31;

    __shared__ float s_m[WARPS_PER_BLOCK];
    __shared__ float s_d[WARPS_PER_BLOCK];
    __shared__ float s_scale[WARPS_PER_BLOCK];
    __shared__ int   s_is_last;

    // Decoder slice in registers: h = k*128 + lane*4
    const float4* dec4 = reinterpret_cast<const float4*>(dec + (size_t)b * H_DIM);
    float4 dv[HV];
#pragma unroll
    for (int k = 0; k < HV; k++) dv[k] = dec4[k * 32 + lane];

    float4 acc[HV];
#pragma unroll
    for (int k = 0; k < HV; k++) acc[k] = make_float4(0.f, 0.f, 0.f, 0.f);
    float m = -CUDART_INF_F;
    float d = 0.f;

    const int l0 = s * ROWS_PER_SPLIT + warp;    // rows: l0 + j*8, j = 0..31

    // Per-warp ring base (byte address in shared space + float pointer)
    float* ring_f = smem_dyn + warp * STAGES * H_DIM;
    const unsigned int ring_a =
        (unsigned int)__cvta_generic_to_shared(smem_dyn) + warp * STAGES * H_DIM * 4;
    const unsigned int lane16 = lane * 16;

    // ---- prefetch issue: row j -> stage j%3 (each thread copies its own 128B)
    auto issue_row = [&](int j) {
        const char* src = reinterpret_cast<const char*>(
            enc + ((size_t)(l0 + j * WARPS_PER_BLOCK) * B_DIM + b) * H_DIM);
        const unsigned int dst = ring_a + (j % STAGES) * (H_DIM * 4);
#pragma unroll
        for (int k = 0; k < HV; k++)
            CP_ASYNC16(dst + k * 512 + lane16, src + k * 512 + lane16);
        CP_COMMIT();
    };

    issue_row(0);
    issue_row(1);
    issue_row(2);

#pragma unroll 1
    for (int j = 0; j < ROWS_PER_WARP; j++) {
        // Row j complete when pending groups <= (#issued-after-j). Tail shrinks.
        if (j < ROWS_PER_WARP - 2)       CP_WAIT(2);
        else if (j == ROWS_PER_WARP - 2) CP_WAIT(1);
        else                             CP_WAIT(0);

        const float4* rowp =
            reinterpret_cast<const float4*>(ring_f + (j % STAGES) * H_DIM);
        float4 ev[HV];
#pragma unroll
        for (int k = 0; k < HV; k++) ev[k] = rowp[k * 32 + lane];   // LDS, own bytes

        // dot(e, dec)
        float sc = 0.f;
#pragma unroll
        for (int k = 0; k < HV; k++) {
            sc = fmaf(ev[k].x, dv[k].x, sc);
            sc = fmaf(ev[k].y, dv[k].y, sc);
            sc = fmaf(ev[k].z, dv[k].z, sc);
            sc = fmaf(ev[k].w, dv[k].w, sc);
        }
#pragma unroll
        for (int off = 16; off > 0; off >>= 1)
            sc += __shfl_xor_sync(0xffffffffu, sc, off);

        // Refill the stage we just freed (row j+3) BEFORE the long update tail.
        if (j + STAGES < ROWS_PER_WARP) issue_row(j + STAGES);

        // branch-free online softmax update (R3 form)
        float nm    = fmaxf(m, sc);
        float alpha = __expf(m - nm);     // 0 on first iter (m = -inf)
        float w     = __expf(sc - nm);
        d = d * alpha + w;
        m = nm;
#pragma unroll
        for (int k = 0; k < HV; k++) {
            acc[k].x = fmaf(w, ev[k].x, acc[k].x * alpha);
            acc[k].y = fmaf(w, ev[k].y, acc[k].y * alpha);
            acc[k].z = fmaf(w, ev[k].z, acc[k].z * alpha);
            acc[k].w = fmaf(w, ev[k].w, acc[k].w * alpha);
        }
    }

    // ---- in-block flash combine of the 8 warp partials ----
    __syncthreads();                      // all cp.async done (each thread waited 0)
    float* s_acc = smem_dyn;              // reuse ring as [8][1024]
#pragma unroll
    for (int k = 0; k < HV; k++)
        *reinterpret_cast<float4*>(&s_acc[warp * H_DIM + k * 128 + lane * 4]) = acc[k];
    if (lane == 0) { s_m[warp] = m; s_d[warp] = d; }
    __syncthreads();

    if (threadIdx.x == 0) {
        float M = -CUDART_INF_F;
#pragma unroll
        for (int w = 0; w < WARPS_PER_BLOCK; w++) M = fmaxf(M, s_m[w]);
        float D = 0.f;
#pragma unroll
        for (int w = 0; w < WARPS_PER_BLOCK; w++) {
            float sc = __expf(s_m[w] - M);
            s_scale[w] = sc;
            D += s_d[w] * sc;
        }
        const int pid = b * SPLITS + s;
        g_m[pid] = M;
        g_d[pid] = D;
    }
    __syncthreads();

    // Each thread reduces 4 h-positions across the 8 warp slots (float4).
    {
        const int h = threadIdx.x * 4;
        float4 sum = make_float4(0.f, 0.f, 0.f, 0.f);
#pragma unroll
        for (int w = 0; w < WARPS_PER_BLOCK; w++) {
            float sc = s_scale[w];
            float4 v = *reinterpret_cast<const float4*>(&s_acc[w * H_DIM + h]);
            sum.x = fmaf(sc, v.x, sum.x);
            sum.y = fmaf(sc, v.y, sum.y);
            sum.z = fmaf(sc, v.z, sum.z);
            sum.w = fmaf(sc, v.w, sum.w);
        }
        const int pid = b * SPLITS + s;
        *reinterpret_cast<float4*>(&g_ctx[(size_t)pid * H_DIM + h]) = sum;
    }

    // ---- last-CTA-per-b cross-split combine ----
    __threadfence();
    if (threadIdx.x == 0)
        s_is_last = (atomicAdd(&g_cnt[b], 1) == SPLITS - 1) ? 1 : 0;
    __syncthreads();
    if (!s_is_last) return;

    __threadfence();   // acquire: order reads of peers' partials after the atomic

    float M = -CUDART_INF_F;
#pragma unroll
    for (int p = 0; p < SPLITS; p++) M = fmaxf(M, g_m[b * SPLITS + p]);
    float D = 0.f;
    float scale[SPLITS];
#pragma unroll
    for (int p = 0; p < SPLITS; p++) {
        scale[p] = __expf(g_m[b * SPLITS + p] - M);
        D += g_d[b * SPLITS + p] * scale[p];
    }
    const float invD = 1.f / D;

    {
        const int h = threadIdx.x * 4;
        float4 sum = make_float4(0.f, 0.f, 0.f, 0.f);
#pragma unroll
        for (int p = 0; p < SPLITS; p++) {
            const float sc = scale[p] * invD;
            float4 v = *reinterpret_cast<const float4*>(
                &g_ctx[((size_t)(b * SPLITS + p)) * H_DIM + h]);
            sum.x = fmaf(sc, v.x, sum.x);
            sum.y = fmaf(sc, v.y, sum.y);
            sum.z = fmaf(sc, v.z, sum.z);
            sum.w = fmaf(sc, v.w, sum.w);
        }
        *reinterpret_cast<float4*>(&out[(size_t)b * H_DIM + h]) = sum;
    }

    if (threadIdx.x == 0) g_cnt[b] = 0;   // reset for next graph replay
}

// ---------------------------------------------------------------------------
extern "C" void kernel_launch(void* const* d_in, const int* in_sizes, int n_in,
                              void* d_out, int out_size)
{
    const float* enc = (const float*)d_in[0];   // [1024, 64, 1024]
    const float* dec = (const float*)d_in[1];   // [1, 64, 1024]
    float* out = (float*)d_out;                 // [64, 1024]

    const int dyn_smem = RING_FLOATS * 4;       // 96 KB
    cudaFuncSetAttribute(attn_fused,
                         cudaFuncAttributeMaxDynamicSharedMemorySize, dyn_smem);

    dim3 grid(SPLITS, B_DIM);
    attn_fused<<<grid, 256, dyn_smem>>>(enc, dec, out);
}

// round 10
// speedup vs baseline: 1.1968x; 1.0471x over previous
#include <cuda_runtime.h>
#include <cuda_bf16.h>
#include <math_constants.h>
#include <cstdint>

// Problem shape (fixed by the reference)
#define L_DIM 1024
#define B_DIM 64
#define H_DIM 1024
#define N_ROWS (L_DIM * B_DIM)           // flat rows, b-major: r = b*1024 + l

#define G_CTAS 148                       // exactly 1 CTA per SM -> perfect balance
#define THREADS 512
#define WARPS_PER_BLOCK 16
#define HV 8                             // float4 vectors per thread (H/128)
#define MAXC 8                           // max contributing slots per b (<= 5 actual)

// Scratch: one partial per (cta, segment). 296 slots x 4 KB ~= 1.2 MB.
__device__ float g_ctx[2 * G_CTAS * H_DIM];
__device__ float g_m[2 * G_CTAS];
__device__ float g_d[2 * G_CTAS];
__device__ int   g_tag[2 * G_CTAS];      // b+1 of the partial in this slot
__device__ int   g_rows[B_DIM];          // rows accumulated per b; reset by combiner

extern __shared__ float s_acc[];         // [16][1024] = 64 KB (dynamic)

// ---------------------------------------------------------------------------
// R3's exact hot loop (branch-free online softmax, __ldcs, reg-resident dec),
// repartitioned: 148 CTAs x 16 warps, flat balanced row ranges.
// ---------------------------------------------------------------------------
__global__ __launch_bounds__(THREADS, 1)
void attn_fused(const float* __restrict__ enc,   // [L, B, H]
                const float* __restrict__ dec,   // [1, B, H]
                float* __restrict__ out)         // [B, H]
{
    const int cta  = blockIdx.x;
    const int warp = threadIdx.x >> 5;
    const int lane = threadIdx.x & 31;

    __shared__ float s_m[WARPS_PER_BLOCK];
    __shared__ float s_d[WARPS_PER_BLOCK];
    __shared__ float s_scale[WARPS_PER_BLOCK];
    __shared__ int   s_is_last;

    const int r0 = (int)(((long long)cta * N_ROWS) / G_CTAS);
    const int r1 = (int)(((long long)(cta + 1) * N_ROWS) / G_CTAS);
    const int b0   = r0 >> 10;
    const int bend = (r1 - 1) >> 10;
    const int nseg = (bend > b0) ? 2 : 1;

    for (int seg = 0; seg < nseg; seg++) {
        const int b  = b0 + seg;
        const int s0 = max(r0, b << 10);
        const int s1 = min(r1, (b + 1) << 10);
        const int seg_rows = s1 - s0;

        // Decoder slice in registers: h = k*128 + lane*4
        const float4* dec4 = reinterpret_cast<const float4*>(dec + (size_t)b * H_DIM);
        float4 dv[HV];
#pragma unroll
        for (int k = 0; k < HV; k++) dv[k] = dec4[k * 32 + lane];

        float4 acc[HV];
#pragma unroll
        for (int k = 0; k < HV; k++) acc[k] = make_float4(0.f, 0.f, 0.f, 0.f);
        float m = -CUDART_INF_F;
        float d = 0.f;

        for (int r = s0 + warp; r < s1; r += WARPS_PER_BLOCK) {
            const int l = r & 1023;
            const float4* e4 =
                reinterpret_cast<const float4*>(enc + ((size_t)l * B_DIM + b) * H_DIM);
            float4 ev[HV];
#pragma unroll
            for (int k = 0; k < HV; k++) ev[k] = __ldcs(&e4[k * 32 + lane]);  // MLP=8

            // dot(e, dec): per-thread partial, warp butterfly reduce
            float sc = 0.f;
#pragma unroll
            for (int k = 0; k < HV; k++) {
                sc = fmaf(ev[k].x, dv[k].x, sc);
                sc = fmaf(ev[k].y, dv[k].y, sc);
                sc = fmaf(ev[k].z, dv[k].z, sc);
                sc = fmaf(ev[k].w, dv[k].w, sc);
            }
#pragma unroll
            for (int off = 16; off > 0; off >>= 1)
                sc += __shfl_xor_sync(0xffffffffu, sc, off);

            // branch-free online softmax update (R3 form)
            float nm    = fmaxf(m, sc);
            float alpha = __expf(m - nm);   // 0 on first iter (m = -inf)
            float w     = __expf(sc - nm);
            d = d * alpha + w;
            m = nm;
#pragma unroll
            for (int k = 0; k < HV; k++) {
                acc[k].x = fmaf(w, ev[k].x, acc[k].x * alpha);
                acc[k].y = fmaf(w, ev[k].y, acc[k].y * alpha);
                acc[k].z = fmaf(w, ev[k].z, acc[k].z * alpha);
                acc[k].w = fmaf(w, ev[k].w, acc[k].w * alpha);
            }
        }

        // ---- in-block flash combine of the 16 warp partials ----
        __syncthreads();   // protect s_acc reuse across segments
#pragma unroll
        for (int k = 0; k < HV; k++)
            *reinterpret_cast<float4*>(&s_acc[warp * H_DIM + k * 128 + lane * 4]) = acc[k];
        if (lane == 0) { s_m[warp] = m; s_d[warp] = d; }
        __syncthreads();

        const int slot = 2 * cta + seg;
        if (threadIdx.x == 0) {
            float M = -CUDART_INF_F;
#pragma unroll
            for (int w = 0; w < WARPS_PER_BLOCK; w++)
                if (s_d[w] > 0.f) M = fmaxf(M, s_m[w]);
            float D = 0.f;
#pragma unroll
            for (int w = 0; w < WARPS_PER_BLOCK; w++) {
                float sc = (s_d[w] > 0.f) ? __expf(s_m[w] - M) : 0.f;
                s_scale[w] = sc;
                D += s_d[w] * sc;
            }
            g_m[slot] = M;
            g_d[slot] = D;
            g_tag[slot] = b + 1;
        }
        __syncthreads();

        // Each thread reduces 2 h-positions... (512 threads x 2 floats = 1024)
        {
            const int h = threadIdx.x * 2;
            float2 sum = make_float2(0.f, 0.f);
#pragma unroll
            for (int w = 0; w < WARPS_PER_BLOCK; w++) {
                float sc = s_scale[w];
                float2 v = *reinterpret_cast<const float2*>(&s_acc[w * H_DIM + h]);
                sum.x = fmaf(sc, v.x, sum.x);
                sum.y = fmaf(sc, v.y, sum.y);
            }
            *reinterpret_cast<float2*>(&g_ctx[(size_t)slot * H_DIM + h]) = sum;
        }

        // ---- arrival: count rows; the CTA reaching 1024 combines b ----
        __threadfence();
        if (threadIdx.x == 0) {
            int old = atomicAdd(&g_rows[b], seg_rows);
            s_is_last = (old + seg_rows == L_DIM) ? 1 : 0;
        }
        __syncthreads();
        if (!s_is_last) continue;

        __threadfence();   // acquire: order reads of peers' partials after the atomic

        // Candidate contributor CTAs form a contiguous window around b.
        int ic = (int)(((long long)(b << 10) * G_CTAS) / N_ROWS);
        int ilo = max(0, ic - 1);
        int ihi = min(G_CTAS - 1,
                      (int)(((long long)((b + 1) << 10) * G_CTAS) / N_ROWS) + 1);

        int slots[MAXC];
        int nc = 0;
        for (int i = ilo; i <= ihi && nc < MAXC; i++) {
#pragma unroll
            for (int sg = 0; sg < 2; sg++) {
                int sl = 2 * i + sg;
                if (g_tag[sl] == b + 1 && nc < MAXC) slots[nc++] = sl;
            }
        }

        float M = -CUDART_INF_F;
        for (int p = 0; p < nc; p++) M = fmaxf(M, g_m[slots[p]]);
        float D = 0.f;
        float scl[MAXC];
        for (int p = 0; p < nc; p++) {
            scl[p] = __expf(g_m[slots[p]] - M);
            D += g_d[slots[p]] * scl[p];
        }
        const float invD = 1.f / D;

        {
            const int h = threadIdx.x * 2;
            float2 sum = make_float2(0.f, 0.f);
            for (int p = 0; p < nc; p++) {
                const float sc = scl[p] * invD;
                float2 v = *reinterpret_cast<const float2*>(
                    &g_ctx[(size_t)slots[p] * H_DIM + h]);
                sum.x = fmaf(sc, v.x, sum.x);
                sum.y = fmaf(sc, v.y, sum.y);
            }
            *reinterpret_cast<float2*>(&out[(size_t)b * H_DIM + h]) = sum;
        }

        if (threadIdx.x == 0) g_rows[b] = 0;   // reset for next graph replay
    }
}

// ---------------------------------------------------------------------------
extern "C" void kernel_launch(void* const* d_in, const int* in_sizes, int n_in,
                              void* d_out, int out_size)
{
    const float* enc = (const float*)d_in[0];   // [1024, 64, 1024]
    const float* dec = (const float*)d_in[1];   // [1, 64, 1024]
    float* out = (float*)d_out;                 // [64, 1024]

    const int dyn_smem = WARPS_PER_BLOCK * H_DIM * 4;   // 64 KB
    cudaFuncSetAttribute(attn_fused,
                         cudaFuncAttributeMaxDynamicSharedMemorySize, dyn_smem);

    attn_fused<<<G_CTAS, THREADS, dyn_smem>>>(enc, dec, out);
}